// round 5
// baseline (speedup 1.0000x reference)
#include <cuda_runtime.h>
#include <cstdint>

#define Hd 768
#define HV4 192          // Hd / 4 (float4 per row)
#define BGRAPH 256
#define AOUT 3129
#define SSPLIT 6         // row-splits per segment in pooling

// ---- device scratch (no allocations allowed) ----
__device__ int   g_bounds[2][BGRAPH + 1];                       // node / edge segment bounds
__device__ float g_partial[2][SSPLIT][BGRAPH][Hd];              // pooling partials (9.4 MB)
__device__ float g_langg[BGRAPH * 3 * Hd];                      // [256, 2304]
__device__ float g_mid1[BGRAPH * Hd];
__device__ float g_mid2[BGRAPH * Hd];

// Scratch selector: 0 = external pointer, 1 = langg, 2 = mid1, 3 = mid2.
__device__ __forceinline__ float* sel_buf(int sel, float* ext) {
    switch (sel) { case 1: return g_langg; case 2: return g_mid1; case 3: return g_mid2;
                   default: return ext; }
}
__device__ __forceinline__ const float* sel_buf_c(int sel, const float* ext) {
    switch (sel) { case 1: return g_langg; case 2: return g_mid1; case 3: return g_mid2;
                   default: return ext; }
}

__device__ __forceinline__ float4 f4add(float4 a, float4 b) {
    a.x += b.x; a.y += b.y; a.z += b.z; a.w += b.w; return a;
}

// ---- 0. ALL bias pre-inits in one launch. grid=(22, BGRAPH), block=256 ----
// n in [0,768)      -> lang_g[:, 1536+n]  = b_lang[n]
// n in [768,1536)   -> mid1               = b_mid
// n in [1536,2304)  -> mid2               = b_mid2
// n in [2304,5433)  -> pred               = b_ans
__global__ void init_all_kernel(float* __restrict__ pred,
                                const float* __restrict__ b_lang,
                                const float* __restrict__ b_mid,
                                const float* __restrict__ b_mid2,
                                const float* __restrict__ b_ans) {
    const int b = blockIdx.y;
    const int n = blockIdx.x * 256 + threadIdx.x;
    if (n < Hd)             g_langg[b * 3 * Hd + 2 * Hd + n] = b_lang[n];
    else if (n < 2 * Hd)    g_mid1[b * Hd + (n - Hd)]        = b_mid[n - Hd];
    else if (n < 3 * Hd)    g_mid2[b * Hd + (n - 2 * Hd)]    = b_mid2[n - 2 * Hd];
    else {
        const int m = n - 3 * Hd;
        if (m < AOUT)       pred[b * AOUT + m]               = b_ans[m];
    }
}

// ---- 1. segment bounds, once. grid=2 (node, edge), block=257 ----
__global__ void bounds_kernel(const int* __restrict__ node_seg, int nn,
                              const int* __restrict__ edge_seg, int ne) {
    const int* seg = blockIdx.x ? edge_seg : node_seg;
    const int  n   = blockIdx.x ? ne : nn;
    const int  v   = threadIdx.x;                // 0..256
    int lo = 0, hi = n;
    while (lo < hi) { int m = (lo + hi) >> 1; if (seg[m] < v) lo = m + 1; else hi = m; }
    g_bounds[blockIdx.x][v] = lo;
}

// ---- 2. pooling partial sums. grid=(BGRAPH, SSPLIT, 2), block=192 ----
__global__ __launch_bounds__(HV4)
void pool_partial_kernel(const float* __restrict__ node_feat,
                         const float* __restrict__ edge_feat) {
    const int b = blockIdx.x, s = blockIdx.y, z = blockIdx.z;
    const float4* feat = (const float4*)(z ? edge_feat : node_feat);
    const int start = g_bounds[z][b];
    const int end   = g_bounds[z][b + 1];
    const int len   = end - start;
    const int chunk = (len + SSPLIT - 1) / SSPLIT;
    const int r0 = start + s * chunk;
    const int r1 = min(r0 + chunk, end);
    const int c = threadIdx.x;                   // float4 column 0..191

    float4 a0 = {0,0,0,0}, a1 = {0,0,0,0}, a2 = {0,0,0,0}, a3 = {0,0,0,0};
    const float4* p = feat + c;
    int r = r0;
    for (; r + 4 <= r1; r += 4) {
        a0 = f4add(a0, p[(size_t)(r + 0) * HV4]);
        a1 = f4add(a1, p[(size_t)(r + 1) * HV4]);
        a2 = f4add(a2, p[(size_t)(r + 2) * HV4]);
        a3 = f4add(a3, p[(size_t)(r + 3) * HV4]);
    }
    for (; r < r1; ++r) a0 = f4add(a0, p[(size_t)r * HV4]);
    float4 t = f4add(f4add(a0, a1), f4add(a2, a3));
    ((float4*)&g_partial[z][s][b][0])[c] = t;
}

// ---- 3. reduce partials -> lang_g columns. grid=(BGRAPH, 2), block=192 ----
__global__ void pool_reduce_kernel() {
    const int b = blockIdx.x, z = blockIdx.y, c = threadIdx.x;
    float4 acc = {0,0,0,0};
    #pragma unroll
    for (int s = 0; s < SSPLIT; s++)
        acc = f4add(acc, ((const float4*)&g_partial[z][s][b][0])[c]);
    ((float4*)&g_langg[b * (3 * Hd) + z * Hd])[c] = acc;
}

// ---- tiled fp32 GEMM: C[M,N] += op(A) @ W  (bias pre-loaded in C) ----
// BM=BN=64, BK=16, 256 threads, 4x4 tile via packed fma.rn.f32x2.
// Register double-buffered global loads. gridDim.z = k_splits;
// ATOMIC => atomicAdd into pre-initialized C, else direct store of acc+bias.
template <bool RELU_A, bool ATOMIC>
__global__ __launch_bounds__(256)
void gemm_kernel(int a_sel, const float* __restrict__ A_ext, int lda,
                 const float* __restrict__ W,
                 const float* __restrict__ bias,
                 int c_sel, float* __restrict__ C_ext, int c_off, int ldc,
                 int M, int N, int K) {
    const float* A = sel_buf_c(a_sel, A_ext);
    float* C = sel_buf(c_sel, C_ext) + c_off;

    const int BM = 64, BN = 64, BK = 16;
    __shared__ float As[BK][BM + 4];   // row = 272 B (16B-aligned)
    __shared__ float Ws[BK][BN];       // row = 256 B

    const int tid = threadIdx.x;
    const int tx = tid & 15;
    const int ty = tid >> 4;
    const int bm = blockIdx.x * BM;
    const int bn = blockIdx.y * BN;
    const int Kc = K / gridDim.z;
    const int k0 = blockIdx.z * Kc;
    const int kend = k0 + Kc;

    // Per-thread load coordinates (constant across iterations)
    const int ar = tid >> 4, ac = tid & 15;       // + i*16 rows via e = tid + i*256
    const int wr = tid >> 6, wc = tid & 63;

    float ra[4], rw[4];
    auto loadg = [&](int ks) {
        #pragma unroll
        for (int i = 0; i < 4; i++) {
            float v = A[(bm + ar + i * 16) * lda + ks + ac];
            if (RELU_A) v = fmaxf(v, 0.f);
            ra[i] = v;
        }
        #pragma unroll
        for (int i = 0; i < 4; i++) {
            int n = bn + wc;
            rw[i] = (n < N) ? W[(ks + wr + i * 4) * N + n] : 0.f;
        }
    };
    loadg(k0);

    unsigned long long acc2[4][2] = {};   // [i][jp], each packs 2 fp32 along n

    for (int ks = k0; ks < kend; ks += BK) {
        #pragma unroll
        for (int i = 0; i < 4; i++) As[ac][ar + i * 16] = ra[i];
        #pragma unroll
        for (int i = 0; i < 4; i++) Ws[wr + i * 4][wc] = rw[i];
        __syncthreads();

        if (ks + BK < kend) loadg(ks + BK);   // prefetch next tile (latency hidden)

        #pragma unroll
        for (int k = 0; k < BK; k++) {
            float4 a = *reinterpret_cast<const float4*>(&As[k][ty * 4]);
            ulonglong2 b = *reinterpret_cast<const ulonglong2*>(&Ws[k][tx * 4]);
            uint32_t au[4] = {__float_as_uint(a.x), __float_as_uint(a.y),
                              __float_as_uint(a.z), __float_as_uint(a.w)};
            #pragma unroll
            for (int i = 0; i < 4; i++) {
                unsigned long long aa;
                asm("mov.b64 %0, {%1, %1};" : "=l"(aa) : "r"(au[i]));
                asm("fma.rn.f32x2 %0, %1, %2, %0;" : "+l"(acc2[i][0]) : "l"(aa), "l"(b.x));
                asm("fma.rn.f32x2 %0, %1, %2, %0;" : "+l"(acc2[i][1]) : "l"(aa), "l"(b.y));
            }
        }
        __syncthreads();
    }

    #pragma unroll
    for (int i = 0; i < 4; i++) {
        int m = bm + ty * 4 + i;
        #pragma unroll
        for (int jp = 0; jp < 2; jp++) {
            unsigned long long v = acc2[i][jp];
            float lo = __uint_as_float((uint32_t)v);
            float hi = __uint_as_float((uint32_t)(v >> 32));
            int n0 = bn + tx * 4 + jp * 2;
            if (ATOMIC) {
                if (n0 < N)     atomicAdd(&C[m * ldc + n0],     lo);
                if (n0 + 1 < N) atomicAdd(&C[m * ldc + n0 + 1], hi);
            } else {
                if (n0 < N)     C[m * ldc + n0]     = lo + bias[n0];
                if (n0 + 1 < N) C[m * ldc + n0 + 1] = hi + bias[n0 + 1];
            }
        }
    }
}

extern "C" void kernel_launch(void* const* d_in, const int* in_sizes, int n_in,
                              void* d_out, int out_size) {
    const float* node_feat = (const float*)d_in[0];
    const float* edge_feat = (const float*)d_in[1];
    const float* question  = (const float*)d_in[2];
    const int*   node_seg  = (const int*)  d_in[3];
    const int*   edge_seg  = (const int*)  d_in[4];
    const float* W_lang    = (const float*)d_in[5];
    const float* b_lang    = (const float*)d_in[6];
    const float* W_mid     = (const float*)d_in[7];
    const float* b_mid     = (const float*)d_in[8];
    const float* W_mid2    = (const float*)d_in[9];
    const float* b_mid2    = (const float*)d_in[10];
    const float* W_ans     = (const float*)d_in[11];
    const float* b_ans     = (const float*)d_in[12];
    float* pred = (float*)d_out;

    const int Nn = in_sizes[3];
    const int Ne = in_sizes[4];

    // 0. all bias pre-inits, one launch (depends on nothing)
    init_all_kernel<<<dim3((3 * Hd + AOUT + 255) / 256, BGRAPH), 256>>>(
        pred, b_lang, b_mid, b_mid2, b_ans);

    // 1. segment bounds (both tensors)
    bounds_kernel<<<2, BGRAPH + 1>>>(node_seg, Nn, edge_seg, Ne);

    // 2-3. pooling: partials then reduce -> lang_g[:, 0:1536]
    pool_partial_kernel<<<dim3(BGRAPH, SSPLIT, 2), HV4>>>(node_feat, edge_feat);
    pool_reduce_kernel<<<dim3(BGRAPH, 2), HV4>>>();

    // 4. lang = q @ W_lang + b_lang -> lang_g[:, 1536:2304]   (split-K=6)
    gemm_kernel<false, true><<<dim3(4, 12, 6), 256>>>(
        0, question, Hd, W_lang, nullptr, 1, nullptr, 2 * Hd, 3 * Hd, BGRAPH, Hd, Hd);

    // 5. mid1 = lang_g @ W_mid + b_mid                        (split-K=6)
    gemm_kernel<false, true><<<dim3(4, 12, 6), 256>>>(
        1, nullptr, 3 * Hd, W_mid, nullptr, 2, nullptr, 0, Hd, BGRAPH, Hd, 3 * Hd);

    // 6. mid2 = relu(mid1) @ W_mid2 + b_mid2                  (split-K=6)
    gemm_kernel<true, true><<<dim3(4, 12, 6), 256>>>(
        2, nullptr, Hd, W_mid2, nullptr, 3, nullptr, 0, Hd, BGRAPH, Hd, Hd);

    // 7. pred = relu(mid2) @ W_ans + b_ans                    (split-K=2)
    gemm_kernel<true, true><<<dim3(4, (AOUT + 63) / 64, 2), 256>>>(
        3, nullptr, Hd, W_ans, nullptr, 0, pred, 0, AOUT, BGRAPH, AOUT, Hd);
}

// round 6
// speedup vs baseline: 1.0991x; 1.0991x over previous
#include <cuda_runtime.h>
#include <cstdint>

#define Hd 768
#define HV4 192          // Hd / 4 (float4 per row)
#define BGRAPH 256
#define AOUT 3129
#define SSPLIT 6         // row-splits per segment in pooling

// ---- device scratch (no allocations allowed) ----
__device__ int   g_bounds[2][BGRAPH + 1];                       // node / edge segment bounds
__device__ float g_partial[2][SSPLIT][BGRAPH][Hd];              // pooling partials (9.4 MB)
__device__ float g_langg[BGRAPH * 3 * Hd];                      // [256, 2304]
__device__ float g_mid1[BGRAPH * Hd];
__device__ float g_mid2[BGRAPH * Hd];

// Scratch selector: 0 = external pointer, 1 = langg, 2 = mid1, 3 = mid2.
__device__ __forceinline__ float* sel_buf(int sel, float* ext) {
    switch (sel) { case 1: return g_langg; case 2: return g_mid1; case 3: return g_mid2;
                   default: return ext; }
}
__device__ __forceinline__ const float* sel_buf_c(int sel, const float* ext) {
    switch (sel) { case 1: return g_langg; case 2: return g_mid1; case 3: return g_mid2;
                   default: return ext; }
}

__device__ __forceinline__ float4 f4add(float4 a, float4 b) {
    a.x += b.x; a.y += b.y; a.z += b.z; a.w += b.w; return a;
}

// ---- 0. ALL bias pre-inits in one launch. grid=(22, BGRAPH), block=256 ----
__global__ void init_all_kernel(float* __restrict__ pred,
                                const float* __restrict__ b_lang,
                                const float* __restrict__ b_mid,
                                const float* __restrict__ b_mid2,
                                const float* __restrict__ b_ans) {
    const int b = blockIdx.y;
    const int n = blockIdx.x * 256 + threadIdx.x;
    if (n < Hd)             g_langg[b * 3 * Hd + 2 * Hd + n] = b_lang[n];
    else if (n < 2 * Hd)    g_mid1[b * Hd + (n - Hd)]        = b_mid[n - Hd];
    else if (n < 3 * Hd)    g_mid2[b * Hd + (n - 2 * Hd)]    = b_mid2[n - 2 * Hd];
    else {
        const int m = n - 3 * Hd;
        if (m < AOUT)       pred[b * AOUT + m]               = b_ans[m];
    }
}

// ---- 1. segment bounds, once. grid=2 (node, edge), block=257 ----
__global__ void bounds_kernel(const int* __restrict__ node_seg, int nn,
                              const int* __restrict__ edge_seg, int ne) {
    const int* seg = blockIdx.x ? edge_seg : node_seg;
    const int  n   = blockIdx.x ? ne : nn;
    const int  v   = threadIdx.x;                // 0..256
    int lo = 0, hi = n;
    while (lo < hi) { int m = (lo + hi) >> 1; if (seg[m] < v) lo = m + 1; else hi = m; }
    g_bounds[blockIdx.x][v] = lo;
}

// ---- 2. pooling partial sums. grid=(BGRAPH, SSPLIT, 2), block=192 ----
// Block (b, s, z): sums a contiguous 1/S row-chunk of segment b of tensor z,
// full row width via float4 (LDG.128, 8-row unroll => per-thread MLP 8).
__global__ __launch_bounds__(HV4)
void pool_partial_kernel(const float* __restrict__ node_feat,
                         const float* __restrict__ edge_feat) {
    const int b = blockIdx.x, s = blockIdx.y, z = blockIdx.z;
    const float4* feat = (const float4*)(z ? edge_feat : node_feat);
    const int start = g_bounds[z][b];
    const int end   = g_bounds[z][b + 1];
    const int len   = end - start;
    const int chunk = (len + SSPLIT - 1) / SSPLIT;
    const int r0 = start + s * chunk;
    const int r1 = min(r0 + chunk, end);
    const int c = threadIdx.x;                   // float4 column 0..191

    float4 a0 = {0,0,0,0}, a1 = {0,0,0,0}, a2 = {0,0,0,0}, a3 = {0,0,0,0};
    float4 a4 = {0,0,0,0}, a5 = {0,0,0,0}, a6 = {0,0,0,0}, a7 = {0,0,0,0};
    const float4* p = feat + c;
    int r = r0;
    for (; r + 8 <= r1; r += 8) {
        a0 = f4add(a0, p[(size_t)(r + 0) * HV4]);
        a1 = f4add(a1, p[(size_t)(r + 1) * HV4]);
        a2 = f4add(a2, p[(size_t)(r + 2) * HV4]);
        a3 = f4add(a3, p[(size_t)(r + 3) * HV4]);
        a4 = f4add(a4, p[(size_t)(r + 4) * HV4]);
        a5 = f4add(a5, p[(size_t)(r + 5) * HV4]);
        a6 = f4add(a6, p[(size_t)(r + 6) * HV4]);
        a7 = f4add(a7, p[(size_t)(r + 7) * HV4]);
    }
    for (; r < r1; ++r) a0 = f4add(a0, p[(size_t)r * HV4]);
    float4 t = f4add(f4add(f4add(a0, a1), f4add(a2, a3)),
                     f4add(f4add(a4, a5), f4add(a6, a7)));
    ((float4*)&g_partial[z][s][b][0])[c] = t;
}

// ---- 3. reduce partials -> lang_g columns. grid=(BGRAPH, 2), block=192 ----
__global__ void pool_reduce_kernel() {
    const int b = blockIdx.x, z = blockIdx.y, c = threadIdx.x;
    float4 acc = {0,0,0,0};
    #pragma unroll
    for (int s = 0; s < SSPLIT; s++)
        acc = f4add(acc, ((const float4*)&g_partial[z][s][b][0])[c]);
    ((float4*)&g_langg[b * (3 * Hd) + z * Hd])[c] = acc;
}

// ---- tiled fp32 GEMM: C[M,N] (+)= op(A) @ W (+ bias)  [R4 proven version] ----
// BM=BN=64, BK=16, 256 threads, 4x4 tile, float4 LDS in inner loop.
// gridDim.z = k_splits; ATOMIC => atomicAdd into bias-preinit C.
template <bool RELU_A, bool ATOMIC>
__global__ __launch_bounds__(256)
void gemm_kernel(int a_sel, const float* __restrict__ A_ext, int lda,
                 const float* __restrict__ W,
                 const float* __restrict__ bias,
                 int c_sel, float* __restrict__ C_ext, int c_off, int ldc,
                 int M, int N, int K) {
    const float* A = sel_buf_c(a_sel, A_ext);
    float* C = sel_buf(c_sel, C_ext) + c_off;

    const int BM = 64, BN = 64, BK = 16;
    __shared__ float As[BK][BM + 4];   // row = 272 B (16B-aligned)
    __shared__ float Ws[BK][BN];

    const int tid = threadIdx.x;
    const int tx = tid & 15;
    const int ty = tid >> 4;
    const int bm = blockIdx.x * BM;
    const int bn = blockIdx.y * BN;
    const int Kc = K / gridDim.z;
    const int k0 = blockIdx.z * Kc;

    float acc[4][4] = {};

    for (int ks = k0; ks < k0 + Kc; ks += BK) {
        #pragma unroll
        for (int i = 0; i < 4; i++) {
            int e = tid + i * 256;
            int r = e >> 4, c = e & 15;
            float v = A[(bm + r) * lda + ks + c];
            if (RELU_A) v = fmaxf(v, 0.f);
            As[c][r] = v;
        }
        #pragma unroll
        for (int i = 0; i < 4; i++) {
            int e = tid + i * 256;
            int r = e >> 6, c = e & 63;
            int n = bn + c;
            Ws[r][c] = (n < N) ? W[(ks + r) * N + n] : 0.f;
        }
        __syncthreads();

        #pragma unroll
        for (int k = 0; k < BK; k++) {
            float4 a = *reinterpret_cast<const float4*>(&As[k][ty * 4]);
            float4 b = *reinterpret_cast<const float4*>(&Ws[k][tx * 4]);
            const float av[4] = {a.x, a.y, a.z, a.w};
            const float bv[4] = {b.x, b.y, b.z, b.w};
            #pragma unroll
            for (int i = 0; i < 4; i++)
                #pragma unroll
                for (int j = 0; j < 4; j++)
                    acc[i][j] += av[i] * bv[j];
        }
        __syncthreads();
    }

    #pragma unroll
    for (int i = 0; i < 4; i++) {
        int m = bm + ty * 4 + i;
        #pragma unroll
        for (int j = 0; j < 4; j++) {
            int n = bn + tx * 4 + j;
            if (n < N) {
                if (ATOMIC) atomicAdd(&C[m * ldc + n], acc[i][j]);
                else        C[m * ldc + n] = acc[i][j] + bias[n];
            }
        }
    }
}

extern "C" void kernel_launch(void* const* d_in, const int* in_sizes, int n_in,
                              void* d_out, int out_size) {
    const float* node_feat = (const float*)d_in[0];
    const float* edge_feat = (const float*)d_in[1];
    const float* question  = (const float*)d_in[2];
    const int*   node_seg  = (const int*)  d_in[3];
    const int*   edge_seg  = (const int*)  d_in[4];
    const float* W_lang    = (const float*)d_in[5];
    const float* b_lang    = (const float*)d_in[6];
    const float* W_mid     = (const float*)d_in[7];
    const float* b_mid     = (const float*)d_in[8];
    const float* W_mid2    = (const float*)d_in[9];
    const float* b_mid2    = (const float*)d_in[10];
    const float* W_ans     = (const float*)d_in[11];
    const float* b_ans     = (const float*)d_in[12];
    float* pred = (float*)d_out;

    const int Nn = in_sizes[3];
    const int Ne = in_sizes[4];

    // 0. all bias pre-inits, one launch (depends on nothing)
    init_all_kernel<<<dim3((3 * Hd + AOUT + 255) / 256, BGRAPH), 256>>>(
        pred, b_lang, b_mid, b_mid2, b_ans);

    // 1. segment bounds (both tensors)
    bounds_kernel<<<2, BGRAPH + 1>>>(node_seg, Nn, edge_seg, Ne);

    // 2-3. pooling: partials then reduce -> lang_g[:, 0:1536]
    pool_partial_kernel<<<dim3(BGRAPH, SSPLIT, 2), HV4>>>(node_feat, edge_feat);
    pool_reduce_kernel<<<dim3(BGRAPH, 2), HV4>>>();

    // 4. lang = q @ W_lang + b_lang -> lang_g[:, 1536:2304]   (split-K=6)
    gemm_kernel<false, true><<<dim3(4, 12, 6), 256>>>(
        0, question, Hd, W_lang, nullptr, 1, nullptr, 2 * Hd, 3 * Hd, BGRAPH, Hd, Hd);

    // 5. mid1 = lang_g @ W_mid + b_mid                        (split-K=6)
    gemm_kernel<false, true><<<dim3(4, 12, 6), 256>>>(
        1, nullptr, 3 * Hd, W_mid, nullptr, 2, nullptr, 0, Hd, BGRAPH, Hd, 3 * Hd);

    // 6. mid2 = relu(mid1) @ W_mid2 + b_mid2                  (split-K=6)
    gemm_kernel<true, true><<<dim3(4, 12, 6), 256>>>(
        2, nullptr, Hd, W_mid2, nullptr, 3, nullptr, 0, Hd, BGRAPH, Hd, Hd);

    // 7. pred = relu(mid2) @ W_ans + b_ans                    (split-K=2)
    gemm_kernel<true, true><<<dim3(4, (AOUT + 63) / 64, 2), 256>>>(
        3, nullptr, Hd, W_ans, nullptr, 0, pred, 0, AOUT, BGRAPH, AOUT, Hd);
}

// round 7
// speedup vs baseline: 1.1146x; 1.0140x over previous
#include <cuda_runtime.h>
#include <cstdint>

#define Hd 768
#define HV4 192          // Hd / 4 (float4 per row)
#define BGRAPH 256
#define AOUT 3129
#define SSPLIT 6         // row-splits per segment in pooling

// ---- device scratch (no allocations allowed) ----
__device__ int   g_bounds[2][BGRAPH + 1];                       // node / edge segment bounds
__device__ float g_langg[BGRAPH * 3 * Hd];                      // [256, 2304]
__device__ float g_mid1[BGRAPH * Hd];
__device__ float g_mid2[BGRAPH * Hd];

// Scratch selector: 0 = external pointer, 1 = langg, 2 = mid1, 3 = mid2.
__device__ __forceinline__ float* sel_buf(int sel, float* ext) {
    switch (sel) { case 1: return g_langg; case 2: return g_mid1; case 3: return g_mid2;
                   default: return ext; }
}
__device__ __forceinline__ const float* sel_buf_c(int sel, const float* ext) {
    switch (sel) { case 1: return g_langg; case 2: return g_mid1; case 3: return g_mid2;
                   default: return ext; }
}

__device__ __forceinline__ float4 f4add(float4 a, float4 b) {
    a.x += b.x; a.y += b.y; a.z += b.z; a.w += b.w; return a;
}

// ---- 0. ALL pre-inits in one launch. grid=(28, BGRAPH), block=256 ----
// n in [0,1536)        -> lang_g[:, n]        = 0        (atomic pool target)
// n in [1536,2304)     -> lang_g[:, n]        = b_lang[n-1536]
// n in [2304,3072)     -> mid1                = b_mid
// n in [3072,3840)     -> mid2                = b_mid2
// n in [3840,3840+A)   -> pred                = b_ans
__global__ void init_all_kernel(float* __restrict__ pred,
                                const float* __restrict__ b_lang,
                                const float* __restrict__ b_mid,
                                const float* __restrict__ b_mid2,
                                const float* __restrict__ b_ans) {
    const int b = blockIdx.y;
    const int n = blockIdx.x * 256 + threadIdx.x;
    if (n < 2 * Hd)         g_langg[b * 3 * Hd + n]           = 0.f;
    else if (n < 3 * Hd)    g_langg[b * 3 * Hd + n]           = b_lang[n - 2 * Hd];
    else if (n < 4 * Hd)    g_mid1[b * Hd + (n - 3 * Hd)]     = b_mid[n - 3 * Hd];
    else if (n < 5 * Hd)    g_mid2[b * Hd + (n - 4 * Hd)]     = b_mid2[n - 4 * Hd];
    else {
        const int m = n - 5 * Hd;
        if (m < AOUT)       pred[b * AOUT + m]                = b_ans[m];
    }
}

// ---- 1. segment bounds, once. grid=2 (node, edge), block=257 ----
__global__ void bounds_kernel(const int* __restrict__ node_seg, int nn,
                              const int* __restrict__ edge_seg, int ne) {
    const int* seg = blockIdx.x ? edge_seg : node_seg;
    const int  n   = blockIdx.x ? ne : nn;
    const int  v   = threadIdx.x;                // 0..256
    int lo = 0, hi = n;
    while (lo < hi) { int m = (lo + hi) >> 1; if (seg[m] < v) lo = m + 1; else hi = m; }
    g_bounds[blockIdx.x][v] = lo;
}

// ---- 2. pooling. grid=(BGRAPH, SSPLIT, 2), block=192 ----
// Block (b, s, z): sums a contiguous 1/S row-chunk of segment b of tensor z,
// full row width via float4 (LDG.128, 4-row unroll => MLP_p1 = 4, calibrated),
// then atomicAdds its partial row directly into lang_g (pre-zeroed).
__global__ __launch_bounds__(HV4)
void pool_kernel(const float* __restrict__ node_feat,
                 const float* __restrict__ edge_feat) {
    const int b = blockIdx.x, s = blockIdx.y, z = blockIdx.z;
    const float4* feat = (const float4*)(z ? edge_feat : node_feat);
    const int start = g_bounds[z][b];
    const int end   = g_bounds[z][b + 1];
    const int len   = end - start;
    const int chunk = (len + SSPLIT - 1) / SSPLIT;
    const int r0 = start + s * chunk;
    const int r1 = min(r0 + chunk, end);
    const int c = threadIdx.x;                   // float4 column 0..191

    float4 a0 = {0,0,0,0}, a1 = {0,0,0,0}, a2 = {0,0,0,0}, a3 = {0,0,0,0};
    const float4* p = feat + c;
    int r = r0;
    for (; r + 4 <= r1; r += 4) {
        a0 = f4add(a0, p[(size_t)(r + 0) * HV4]);
        a1 = f4add(a1, p[(size_t)(r + 1) * HV4]);
        a2 = f4add(a2, p[(size_t)(r + 2) * HV4]);
        a3 = f4add(a3, p[(size_t)(r + 3) * HV4]);
    }
    for (; r < r1; ++r) a0 = f4add(a0, p[(size_t)r * HV4]);
    float4 t = f4add(f4add(a0, a1), f4add(a2, a3));

    float* dst = &g_langg[b * (3 * Hd) + z * Hd + c * 4];
    atomicAdd(dst + 0, t.x);
    atomicAdd(dst + 1, t.y);
    atomicAdd(dst + 2, t.z);
    atomicAdd(dst + 3, t.w);
}

// ---- tiled fp32 GEMM: C[M,N] (+)= op(A) @ W (+ bias)  [R4 proven version] ----
// BM=BN=64, BK=16, 256 threads, 4x4 tile, float4 LDS in inner loop.
// gridDim.z = k_splits; ATOMIC => atomicAdd into bias-preinit C.
template <bool RELU_A, bool ATOMIC>
__global__ __launch_bounds__(256)
void gemm_kernel(int a_sel, const float* __restrict__ A_ext, int lda,
                 const float* __restrict__ W,
                 const float* __restrict__ bias,
                 int c_sel, float* __restrict__ C_ext, int c_off, int ldc,
                 int M, int N, int K) {
    const float* A = sel_buf_c(a_sel, A_ext);
    float* C = sel_buf(c_sel, C_ext) + c_off;

    const int BM = 64, BN = 64, BK = 16;
    __shared__ float As[BK][BM + 4];   // row = 272 B (16B-aligned)
    __shared__ float Ws[BK][BN];

    const int tid = threadIdx.x;
    const int tx = tid & 15;
    const int ty = tid >> 4;
    const int bm = blockIdx.x * BM;
    const int bn = blockIdx.y * BN;
    const int Kc = K / gridDim.z;
    const int k0 = blockIdx.z * Kc;

    float acc[4][4] = {};

    for (int ks = k0; ks < k0 + Kc; ks += BK) {
        #pragma unroll
        for (int i = 0; i < 4; i++) {
            int e = tid + i * 256;
            int r = e >> 4, c = e & 15;
            float v = A[(bm + r) * lda + ks + c];
            if (RELU_A) v = fmaxf(v, 0.f);
            As[c][r] = v;
        }
        #pragma unroll
        for (int i = 0; i < 4; i++) {
            int e = tid + i * 256;
            int r = e >> 6, c = e & 63;
            int n = bn + c;
            Ws[r][c] = (n < N) ? W[(ks + r) * N + n] : 0.f;
        }
        __syncthreads();

        #pragma unroll
        for (int k = 0; k < BK; k++) {
            float4 a = *reinterpret_cast<const float4*>(&As[k][ty * 4]);
            float4 b = *reinterpret_cast<const float4*>(&Ws[k][tx * 4]);
            const float av[4] = {a.x, a.y, a.z, a.w};
            const float bv[4] = {b.x, b.y, b.z, b.w};
            #pragma unroll
            for (int i = 0; i < 4; i++)
                #pragma unroll
                for (int j = 0; j < 4; j++)
                    acc[i][j] += av[i] * bv[j];
        }
        __syncthreads();
    }

    #pragma unroll
    for (int i = 0; i < 4; i++) {
        int m = bm + ty * 4 + i;
        #pragma unroll
        for (int j = 0; j < 4; j++) {
            int n = bn + tx * 4 + j;
            if (n < N) {
                if (ATOMIC) atomicAdd(&C[m * ldc + n], acc[i][j]);
                else        C[m * ldc + n] = acc[i][j] + bias[n];
            }
        }
    }
}

extern "C" void kernel_launch(void* const* d_in, const int* in_sizes, int n_in,
                              void* d_out, int out_size) {
    const float* node_feat = (const float*)d_in[0];
    const float* edge_feat = (const float*)d_in[1];
    const float* question  = (const float*)d_in[2];
    const int*   node_seg  = (const int*)  d_in[3];
    const int*   edge_seg  = (const int*)  d_in[4];
    const float* W_lang    = (const float*)d_in[5];
    const float* b_lang    = (const float*)d_in[6];
    const float* W_mid     = (const float*)d_in[7];
    const float* b_mid     = (const float*)d_in[8];
    const float* W_mid2    = (const float*)d_in[9];
    const float* b_mid2    = (const float*)d_in[10];
    const float* W_ans     = (const float*)d_in[11];
    const float* b_ans     = (const float*)d_in[12];
    float* pred = (float*)d_out;

    const int Nn = in_sizes[3];
    const int Ne = in_sizes[4];

    // 0. all pre-inits (zeros + biases), one launch (depends on nothing)
    init_all_kernel<<<dim3((5 * Hd + AOUT + 255) / 256, BGRAPH), 256>>>(
        pred, b_lang, b_mid, b_mid2, b_ans);

    // 1. segment bounds (both tensors)
    bounds_kernel<<<2, BGRAPH + 1>>>(node_seg, Nn, edge_seg, Ne);

    // 2. pooling -> lang_g[:, 0:1536] via direct atomics (no reduce pass)
    pool_kernel<<<dim3(BGRAPH, SSPLIT, 2), HV4>>>(node_feat, edge_feat);

    // 3. lang = q @ W_lang + b_lang -> lang_g[:, 1536:2304]   (split-K=6)
    gemm_kernel<false, true><<<dim3(4, 12, 6), 256>>>(
        0, question, Hd, W_lang, nullptr, 1, nullptr, 2 * Hd, 3 * Hd, BGRAPH, Hd, Hd);

    // 4. mid1 = lang_g @ W_mid + b_mid                        (split-K=6)
    gemm_kernel<false, true><<<dim3(4, 12, 6), 256>>>(
        1, nullptr, 3 * Hd, W_mid, nullptr, 2, nullptr, 0, Hd, BGRAPH, Hd, 3 * Hd);

    // 5. mid2 = relu(mid1) @ W_mid2 + b_mid2                  (split-K=6)
    gemm_kernel<true, true><<<dim3(4, 12, 6), 256>>>(
        2, nullptr, Hd, W_mid2, nullptr, 3, nullptr, 0, Hd, BGRAPH, Hd, Hd);

    // 6. pred = relu(mid2) @ W_ans + b_ans                    (split-K=2)
    gemm_kernel<true, true><<<dim3(4, (AOUT + 63) / 64, 2), 256>>>(
        3, nullptr, Hd, W_ans, nullptr, 0, pred, 0, AOUT, BGRAPH, AOUT, Hd);
}